// round 6
// baseline (speedup 1.0000x reference)
#include <cuda_runtime.h>
#include <cuda_bf16.h>
#include <math.h>

// Problem constants
#define BB 2
#define LL 1024
#define DD 768
#define HH 12
#define NS 256
#define WW 8
#define TK 50
#define NT 66
#define NR 57
#define NN 20
#define NPAIR ((TK*(TK-1))/2)   // 1225
#define NC (NR+NN)              // 77
#define NE (2*NR+2*NN)          // 154

// Output layout (flattened f32 concat, guarded by out_size)
#define SZ_SCORES (BB*TK*TK*58)   // 290000
#define SZ_PREDS  (BB*TK*TK)      // 5000
#define SZ_PM     (BB*TK*TK)      // 5000
#define SZ_TOP    (BB*TK)         // 100

// Zero-fill extents for s1-side accumulators (eterm, swm, gg)
#define ZET  (BB*TK*NE)
#define ZSWM (BB*LL*NC)
#define ZGG  (BB*NPAIR*NC)
#define ZTOT (ZET+ZSWM+ZGG)
#define PREP_BLOCKS ((ZTOT + 255)/256)

// k_tA extents: zero ts + qsum, transpose anchor, probe
#define ZTS (BB*LL*NT)           // 135168
#define TA_BLOCKS ((ZTS + 255)/256)

// Scratch (static device arrays)
__device__ float g_ts[BB*LL*NT + 64];   // token-level scores [b][l][t] (+pad for 17-wide reads)
__device__ float g_embs[BB*NS*DD];
__device__ int   g_top[BB*TK];
__device__ int   g_trig[BB*TK];
__device__ float g_eterm[BB*TK*NE];
__device__ float g_swm[BB*LL*NC];
__device__ float g_ae[BB*TK*HH*LL];
__device__ float g_q[BB*NPAIR*LL];      // unnormalized q
__device__ float g_qsum[BB*NPAIR];
__device__ float g_gg[BB*NPAIR*NC];     // unnormalized gg
__device__ float g_WT[DD*(NT+NE+NC)];   // anchorT | [W1|W2|M1|M2]T | [W3|M3]T
__device__ int   g_btmode;              // 0=uint8 bool, 1=int32, 2=float32

// ---------------------------------------------------------------------------
// k_tA (main stream, first): anchor transpose + zero ts/qsum + dtype probe
// ---------------------------------------------------------------------------
__global__ void k_tA(const float* __restrict__ anchor,
                     const unsigned char* __restrict__ bt) {
    int i = blockIdx.x * blockDim.x + threadIdx.x;
    if (i == 0) {
        int mode = 1;
        bool nonbin = false, oddone = false;
        for (int t = 0; t < NT; ++t) {
            unsigned char v = bt[t];
            if (v > 1) nonbin = true;
            else if (v == 1 && (t & 3) != 0) oddone = true;
        }
        if (nonbin) mode = 2;
        else if (oddone) mode = 0;
        g_btmode = mode;
    }
    if (i < ZTS) g_ts[i] = 0.f;
    if (i < BB*NPAIR) g_qsum[i] = 0.f;
    if (i < DD*NT) {
        int d = i / NT, t = i % NT;
        g_WT[i] = anchor[t*DD + d];
    }
}

// ---------------------------------------------------------------------------
// Off-critical-path prep (s1): W12T/WM3T transposes + zero-fill + span embs
// ---------------------------------------------------------------------------
__global__ void k_prep_embs(const float* __restrict__ seq,
                            const int* __restrict__ starts,
                            const int* __restrict__ lens,
                            const float* __restrict__ rel,
                            const float* __restrict__ nota) {
    int bx = blockIdx.x;
    int tid = threadIdx.x;
    if (bx < NS*BB) {
        int n = bx & (NS-1), b = bx >> 8;
        if (tid < DD/4) {
            int st = starts[b*NS+n];
            int le = lens[b*NS+n];
            float wt = 1.0f / (float)(le + 1);
            const float4* sb4 = (const float4*)(seq + (size_t)b*LL*DD);
            float4 acc = make_float4(0.f,0.f,0.f,0.f);
            for (int w = 0; w <= le; ++w) {
                int p = st + w; if (p > LL-1) p = LL-1;
                float4 v = sb4[(size_t)p*(DD/4) + tid];
                acc.x += v.x; acc.y += v.y; acc.z += v.z; acc.w += v.w;
            }
            acc.x *= wt; acc.y *= wt; acc.z *= wt; acc.w *= wt;
            ((float4*)(g_embs + ((size_t)b*NS + n)*DD))[tid] = acc;
        }
        return;
    }
    int i = (bx - NS*BB)*256 + tid;
    if (i < ZTOT) {
        int z = i;
        if (z < ZET) g_eterm[z] = 0.f;
        else if ((z -= ZET) < ZSWM) g_swm[z] = 0.f;
        else g_gg[z - ZSWM] = 0.f;
    }
    const int totB = DD*NE, totC = DD*NC;
    if (i < totB) {
        int d = i / NE, j = i % NE;
        float v;
        if (j < NR)            v = rel[(size_t)j*3*DD + d];
        else if (j < 2*NR)     v = rel[(size_t)(j-NR)*3*DD + DD + d];
        else if (j < 2*NR+NN)  v = nota[(size_t)(j-2*NR)*3*DD + d];
        else                   v = nota[(size_t)(j-2*NR-NN)*3*DD + DD + d];
        g_WT[DD*NT + i] = v;
    } else if (i < totB + totC) {
        int i3 = i - totB;
        int d = i3 / NC, j = i3 % NC;
        float v = (j < NR) ? rel[(size_t)j*3*DD + 2*DD + d]
                           : nota[(size_t)(j-NR)*3*DD + 2*DD + d];
        g_WT[DD*(NT+NE) + i3] = v;
    }
}

// ---------------------------------------------------------------------------
// Register-tiled GEMM with k-split + atomic epilogue
// ---------------------------------------------------------------------------
template<int MMAX>
__global__ void k_gemm(const float* __restrict__ A, long sAb,
                       const int* __restrict__ gidx, int gsb,
                       const float* __restrict__ W, long sWb,
                       float* __restrict__ C, long sCb,
                       int M, int N, int K) {
    constexpr int TM = 64;
    constexpr int CT = 32;
    constexpr int NPAD = MMAX*CT;
    __shared__ float As[TM*32];
    __shared__ float Ws[32*NPAD];
    int b = blockIdx.y;
    int r0 = blockIdx.x * TM;
    int tid = threadIdx.x;
    const float* Ab = A + (long)b*sAb;
    const float* Wb = W + (long)b*sWb;
    int kchunk = K / gridDim.z;
    int kbase = blockIdx.z * kchunk;

    float acc[8][MMAX];
#pragma unroll
    for (int i = 0; i < 8; ++i)
#pragma unroll
        for (int m = 0; m < MMAX; ++m) acc[i][m] = 0.f;

    int rg = tid >> 5, ct = tid & 31;

    for (int k0 = kbase; k0 < kbase + kchunk; k0 += 32) {
        for (int e = tid; e < TM*32; e += 256) {
            int r = e >> 5, c = e & 31;
            int R = r0 + r; if (R >= M) R = M-1;
            int row = gidx ? gidx[b*gsb + R] : R;
            As[e] = Ab[(long)row*K + k0 + c];
        }
        for (int e = tid; e < 32*NPAD; e += 256) {
            int r = e / NPAD, c = e % NPAD;
            Ws[e] = (c < N) ? Wb[(long)(k0+r)*N + c] : 0.f;
        }
        __syncthreads();
#pragma unroll 8
        for (int kk = 0; kk < 32; ++kk) {
            float wv[MMAX];
#pragma unroll
            for (int m = 0; m < MMAX; ++m) wv[m] = Ws[kk*NPAD + ct + m*CT];
#pragma unroll
            for (int i = 0; i < 8; ++i) {
                float av = As[(rg*8+i)*32 + kk];
#pragma unroll
                for (int m = 0; m < MMAX; ++m) acc[i][m] += av * wv[m];
            }
        }
        __syncthreads();
    }

#pragma unroll
    for (int i = 0; i < 8; ++i) {
        int R = r0 + rg*8 + i;
        if (R < M) {
#pragma unroll
            for (int m = 0; m < MMAX; ++m) {
                int j = ct + m*CT;
                if (j < N) atomicAdd(&C[(long)b*sCb + (long)R*N + j], acc[i][m]);
            }
        }
    }
}

// ---------------------------------------------------------------------------
// Fused pooling + per-span max/argmax + stable top-K.
// 1 block/batch, 1024 threads: thread = (span, quarter-of-66-types).
// ---------------------------------------------------------------------------
__global__ void k_pooltopk(const int* __restrict__ starts,
                           const int* __restrict__ lens,
                           const void* __restrict__ istrig,
                           float* __restrict__ out, int write_top) {
    __shared__ float pmax[1024];
    __shared__ int   pidx[1024];
    __shared__ float sv[NS];
    __shared__ int   scl[NS];
    int b = blockIdx.x;
    int tid = threadIdx.x;
    int span = tid >> 2, part = tid & 3;
    int t0 = part * 17;
    int tcnt = (t0 + 17 <= NT) ? 17 : (NT - t0);   // 17,17,17,15
    int st = starts[b*NS + span];
    int le = lens[b*NS + span];
    float wt = 1.0f / (float)(le + 1);

    float acc[17];
#pragma unroll
    for (int t = 0; t < 17; ++t) acc[t] = 0.f;
    for (int w = 0; w <= le; ++w) {
        int p = st + w; if (p > LL-1) p = LL-1;
        const float* r = g_ts + ((size_t)b*LL + p)*NT + t0;
#pragma unroll
        for (int t = 0; t < 17; ++t) acc[t] += r[t];
    }
    float best = -INFINITY; int bi = t0;
#pragma unroll
    for (int t = 0; t < 17; ++t) {
        if (t < tcnt) {
            float v = acc[t] * wt;
            if (v > best) { best = v; bi = t0 + t; }
        }
    }
    pmax[tid] = best; pidx[tid] = bi;
    __syncthreads();
    if (tid < NS) {
        float mv = pmax[tid*4]; int mi = pidx[tid*4];
#pragma unroll
        for (int p = 1; p < 4; ++p) {
            float v = pmax[tid*4 + p];
            if (v > mv) { mv = v; mi = pidx[tid*4 + p]; }  // parts ascending: ties keep lower t
        }
        sv[tid] = mv; scl[tid] = mi;
    }
    __syncthreads();
    if (tid < NS) {
        float my = sv[tid];
        int rank = 0;
#pragma unroll 8
        for (int j = 0; j < NS; ++j) {
            float vj = sv[j];
            rank += (vj > my) || (vj == my && j < tid);
        }
        if (rank < TK) {
            g_top[b*TK + rank] = tid;
            int c = scl[tid];
            int tv;
            if (g_btmode == 0)      tv = ((const unsigned char*)istrig)[c] != 0;
            else if (g_btmode == 1) tv = ((const int*)istrig)[c] != 0;
            else                    tv = ((const float*)istrig)[c] != 0.0f;
            g_trig[b*TK + rank] = tv;
            if (write_top)
                out[SZ_SCORES + SZ_PREDS + SZ_PM + b*TK + rank] = (float)tid;
        }
    }
}

// ---------------------------------------------------------------------------
// a_e: attention pooling for top-K spans only (float4)
// ---------------------------------------------------------------------------
__global__ void k_ae(const float* __restrict__ att,
                     const int* __restrict__ starts,
                     const int* __restrict__ lens) {
    int h = blockIdx.x, s = blockIdx.y, b = blockIdx.z;
    int n = g_top[b*TK + s];
    int st = starts[b*NS + n], le = lens[b*NS + n];
    float wt = 1.0f / (float)(le + 1);
    const float4* ab4 = (const float4*)(att + ((size_t)(b*HH + h))*LL*LL);
    float4* ob4 = (float4*)(g_ae + (((size_t)b*TK + s)*HH + h)*LL);
    int tid = threadIdx.x;
    float4 acc = make_float4(0.f,0.f,0.f,0.f);
    for (int w = 0; w <= le; ++w) {
        int p = st + w; if (p > LL-1) p = LL-1;
        float4 v = ab4[(size_t)p*(LL/4) + tid];
        acc.x += v.x; acc.y += v.y; acc.z += v.z; acc.w += v.w;
    }
    acc.x *= wt; acc.y *= wt; acc.z *= wt; acc.w *= wt;
    ob4[tid] = acc;
}

// ---------------------------------------------------------------------------
// q kernel: 2D pair tiles; 4 s-slabs in 192KB smem, o streamed in chunks of 4.
// Writes unnormalized q + per-pair sums (via atomics; qsum zeroed in k_tA).
// ---------------------------------------------------------------------------
#define QS 4
#define QO 16
#define QOC 4
#define NST ((TK+QS-1)/QS)   // 13
#define NOT ((TK+QO-1)/QO)   // 4

__device__ __forceinline__ int pair_idx(int s, int o) {
    return s*TK - (s*(s+1))/2 + (o - s - 1);
}

__global__ void k_q() {
    extern __shared__ float4 sA4[];     // QS*HH*LL floats = 192KB
    __shared__ float sred[QS*QOC*8];
    int b = blockIdx.y;
    int st = blockIdx.x % NST, ot = blockIdx.x / NST;
    int s0 = st*QS, o0 = ot*QO;
    {
        int o_hi = o0 + QO - 1; if (o_hi > TK-1) o_hi = TK-1;
        if (o_hi <= s0) return;
    }
    int tid = threadIdx.x;
    for (int idx = tid; idx < QS*HH*(LL/4); idx += 256) {
        int si = idx / (HH*(LL/4));
        int rem = idx % (HH*(LL/4));
        int sc = s0 + si; if (sc > TK-1) sc = TK-1;
        sA4[idx] = ((const float4*)(g_ae + ((size_t)(b*TK + sc)*HH)*LL))[rem];
    }
    __syncthreads();
    int lane = tid & 31, wid = tid >> 5;

    for (int oc = 0; oc < QO; oc += QOC) {
        int ob = o0 + oc;
        if (ob + QOC - 1 <= s0) continue;
        const float4* aeo[QOC];
#pragma unroll
        for (int oo = 0; oo < QOC; ++oo) {
            int o = ob + oo; if (o > TK-1) o = TK-1;
            aeo[oo] = (const float4*)(g_ae + ((size_t)(b*TK + o)*HH)*LL);
        }
        float4 qv[QS][QOC];
#pragma unroll
        for (int si = 0; si < QS; ++si)
#pragma unroll
            for (int oo = 0; oo < QOC; ++oo) qv[si][oo] = make_float4(0,0,0,0);

#pragma unroll
        for (int h = 0; h < HH; ++h) {
            float4 a[QS];
#pragma unroll
            for (int si = 0; si < QS; ++si) a[si] = sA4[(si*HH + h)*(LL/4) + tid];
#pragma unroll
            for (int oo = 0; oo < QOC; ++oo) {
                float4 x = aeo[oo][h*(LL/4) + tid];
#pragma unroll
                for (int si = 0; si < QS; ++si) {
                    qv[si][oo].x += a[si].x * x.x;
                    qv[si][oo].y += a[si].y * x.y;
                    qv[si][oo].z += a[si].z * x.z;
                    qv[si][oo].w += a[si].w * x.w;
                }
            }
        }
#pragma unroll
        for (int oo = 0; oo < QOC; ++oo) {
            int o = ob + oo;
#pragma unroll
            for (int si = 0; si < QS; ++si) {
                int s = s0 + si;
                float ps = 0.f;
                if (o < TK && s < o) {
                    int pr = pair_idx(s, o);
                    ((float4*)(g_q + ((size_t)b*NPAIR + pr)*LL))[tid] = qv[si][oo];
                    float4 v = qv[si][oo];
                    ps = v.x + v.y + v.z + v.w;
                }
                for (int off = 16; off; off >>= 1)
                    ps += __shfl_down_sync(0xffffffffu, ps, off);
                if (lane == 0) sred[(si*QOC + oo)*8 + wid] = ps;
            }
        }
        __syncthreads();
        if (tid < QS*QOC) {
            int si = tid / QOC, oo = tid % QOC;
            int s = s0 + si, o = ob + oo;
            if (o < TK && s < o) {
                float tot = 0.f;
#pragma unroll
                for (int w = 0; w < 8; ++w) tot += sred[tid*8 + w];
                g_qsum[(size_t)b*NPAIR + pair_idx(s, o)] = tot;
            }
        }
        __syncthreads();
    }
}

// ---------------------------------------------------------------------------
// Final scoring (applies 1/qsum normalization to the gg term here)
// ---------------------------------------------------------------------------
__global__ void k_final(float* __restrict__ out, int write_extra) {
    __shared__ float sc[58];
    __shared__ float nv[NN];
    int o = blockIdx.x, s = blockIdx.y, b = blockIdx.z;
    int tid = threadIdx.x;
    int trig = g_trig[b*TK + s];
    int mask = (trig && (s != o)) ? 1 : 0;
    size_t so = ((size_t)b*TK + s)*TK + o;
    float* outs = out + so*58;
    if (!mask) {
        if (tid < 58) outs[tid] = 0.f;
        if (tid == 0 && write_extra) {
            out[SZ_SCORES + so] = 0.f;
            out[SZ_SCORES + SZ_PREDS + so] = 0.f;
        }
        return;
    }
    int lo = s < o ? s : o, hi = s < o ? o : s;
    int pair = lo*TK - (lo*(lo+1))/2 + (hi - lo - 1);
    float rinv = 1.0f / g_qsum[(size_t)b*NPAIR + pair];
    const float* gg = g_gg + ((size_t)b*NPAIR + pair)*NC;
    const float* es = g_eterm + ((size_t)b*TK + s)*NE;
    const float* eo = g_eterm + ((size_t)b*TK + o)*NE;
    if (tid < NR) sc[1 + tid] = es[tid] + eo[NR + tid] + gg[tid]*rinv;
    if (tid < NN) nv[tid] = es[2*NR + tid] + eo[2*NR + NN + tid] + gg[NR + tid]*rinv;
    __syncthreads();
    if (tid == 0) {
        float nm = nv[0];
        for (int m = 1; m < NN; ++m) nm = fmaxf(nm, nv[m]);
        sc[0] = nm;
    }
    __syncthreads();
    if (tid < 58) outs[tid] = sc[tid];
    if (tid == 0) {
        float mx = sc[0]; int mi = 0;
        for (int c = 1; c < 58; ++c) if (sc[c] > mx) { mx = sc[c]; mi = c; }
        if (write_extra) {
            out[SZ_SCORES + so] = (float)mi;
            out[SZ_SCORES + SZ_PREDS + so] = 1.0f;
        }
    }
}

// ---------------------------------------------------------------------------
extern "C" void kernel_launch(void* const* d_in, const int* in_sizes, int n_in,
                              void* d_out, int out_size) {
    const float* seq    = (const float*)d_in[0];
    const float* att    = (const float*)d_in[1];
    const float* anchor = (const float*)d_in[2];
    const float* rel    = (const float*)d_in[3];
    const float* nota   = (const float*)d_in[4];
    const int* starts   = (const int*)d_in[5];
    const int* lens     = (const int*)d_in[6];
    const void* istrig  = d_in[7];
    float* out = (float*)d_out;

    int write_extra = (out_size >= SZ_SCORES + SZ_PREDS + SZ_PM) ? 1 : 0;
    int write_top   = (out_size >= SZ_SCORES + SZ_PREDS + SZ_PM + SZ_TOP) ? 1 : 0;

    void *p_embs, *p_top, *p_eterm, *p_swm, *p_q, *p_gg, *p_wt, *p_ts;
    cudaGetSymbolAddress(&p_embs, g_embs);
    cudaGetSymbolAddress(&p_ts, g_ts);
    cudaGetSymbolAddress(&p_top, g_top);
    cudaGetSymbolAddress(&p_eterm, g_eterm);
    cudaGetSymbolAddress(&p_swm, g_swm);
    cudaGetSymbolAddress(&p_q, g_q);
    cudaGetSymbolAddress(&p_gg, g_gg);
    cudaGetSymbolAddress(&p_wt, g_WT);

    static cudaStream_t s1 = nullptr;
    static cudaEvent_t eF = nullptr, eT = nullptr, eW = nullptr, eE = nullptr;
    static int smem_set = 0;
    if (!s1) {
        cudaStreamCreateWithFlags(&s1, cudaStreamNonBlocking);
        cudaEventCreateWithFlags(&eF, cudaEventDisableTiming);
        cudaEventCreateWithFlags(&eT, cudaEventDisableTiming);
        cudaEventCreateWithFlags(&eW, cudaEventDisableTiming);
        cudaEventCreateWithFlags(&eE, cudaEventDisableTiming);
    }
    if (!smem_set) {
        cudaFuncSetAttribute(k_q, cudaFuncAttributeMaxDynamicSharedMemorySize,
                             QS*HH*LL*(int)sizeof(float));
        smem_set = 1;
    }

    // Fork s1
    cudaEventRecord(eF, 0);
    cudaStreamWaitEvent(s1, eF, 0);

    // s1 (off critical path): weight transposes + zero-fill + embs -> swm -> eterm
    k_prep_embs<<<NS*BB + PREP_BLOCKS, 256, 0, s1>>>(seq, starts, lens, rel, nota);
    k_gemm<3><<<dim3(16, BB, 8), 256, 0, s1>>>(
        seq, (long)LL*DD, nullptr, 0,
        (const float*)p_wt + DD*(NT+NE), 0,
        (float*)p_swm, (long)LL*NC, LL, NC, DD);
    cudaEventRecord(eW, s1);

    // main critical path: tA -> ts GEMM -> pooled scores + topk
    k_tA<<<TA_BLOCKS, 256>>>(anchor, (const unsigned char*)istrig);
    k_gemm<3><<<dim3(16, BB, 8), 256>>>(
        seq, (long)LL*DD, nullptr, 0,
        (const float*)p_wt, 0,
        (float*)p_ts, (long)LL*NT, LL, NT, DD);
    k_pooltopk<<<BB, 1024>>>(starts, lens, istrig, out, write_top);
    cudaEventRecord(eT, 0);

    // s1 tail: eterm (needs top)
    cudaStreamWaitEvent(s1, eT, 0);
    k_gemm<5><<<dim3(1, BB, 24), 256, 0, s1>>>(
        (const float*)p_embs, (long)NS*DD, (const int*)p_top, TK,
        (const float*)p_wt + DD*NT, 0,
        (float*)p_eterm, (long)TK*NE, TK, NE, DD);
    cudaEventRecord(eE, s1);

    // main: ae -> q -> gg -> final
    k_ae<<<dim3(HH, TK, BB), 256>>>(att, starts, lens);
    k_q<<<dim3(NST*NOT, BB), 256, QS*HH*LL*sizeof(float)>>>();
    cudaStreamWaitEvent(0, eW, 0);
    k_gemm<3><<<dim3(20, BB, 16), 256>>>(
        (const float*)p_q, (long)NPAIR*LL, nullptr, 0,
        (const float*)p_swm, (long)LL*NC,
        (float*)p_gg, (long)NPAIR*NC, NPAIR, NC, LL);
    cudaStreamWaitEvent(0, eE, 0);
    k_final<<<dim3(TK, TK, BB), 64>>>(out, write_extra);
}